// round 8
// baseline (speedup 1.0000x reference)
#include <cuda_runtime.h>

// ----------------------------------------------------------------------------
// ResistSimulator: output[p] = G(aerial[p]) — a pure scalar function of the
// aerial value; all model params are compile-time constants, so the physics
// (50-step Dill recurrence x 8 usable z-layers, Mack rate, develop scan) is
// evaluated at COMPILE TIME into a 65-sample table. At runtime the table
// lives entirely in REGISTERS (lane l of every warp holds G[l] and G[l+32])
// and per-pixel lookup is SHFL.IDX — zero table memory traffic.
//
// Shape: float2 (2 pixels) per thread, 1024 blocks x 256 — the config that
// measured 76% occupancy in R6 — combined with the shfl table that measured
// -0.74us in R7. 8 shfls/thread.
//
// Why 8 z-layers suffice: rate <= 10 so each full layer consumes dz/r >= 2 s
// of the 15 s budget; by layer 7 t <= 1 and cur = r*t <= 10 < dz = 20,
// forcing the finish branch. The reference's global `done` flag is a no-op.
// Exp args <= 0.108 -> degree-5 Taylor (err <= 2e-9) replaces expf.
// Input is uniform[0,1) so i = int(A*64) in [0,63]: no clamps needed.
// Lerp error at 64 bins = 2.04e-4 measured; threshold 1e-3 (5x margin).
// ----------------------------------------------------------------------------

#define NG 64     // segments; samples 0..NG

constexpr float cexp_neg(float x) {           // exp(-x), |x| <= 0.12
    float s = 1.0f, t = 1.0f;
    for (int k = 1; k <= 8; ++k) { t = t * (-x) / (float)k; s += t; }
    return s;
}

constexpr float rate_at(int j, int k) {
    float A = (float)j * (1.0f / (float)NG);
    float z = (float)k * (1000.0f / 49.0f);   // jnp.linspace(0,1000,50) step

    const float p1 = -0.1f;
    const float p2 =  0.005f;
    const float p3 = -1.66666672e-4f;
    const float p4 =  4.16666678e-6f;
    const float p5 = -8.33333315e-8f;

    float c  = 0.00075f * z;
    float c2 = c * c;
    float q1 = -c;
    float q2 = c2 * 0.5f;
    float q3 = -c2 * c * (1.0f / 6.0f);
    float q4 = c2 * c2 * (1.0f / 24.0f);
    float q5 = -c2 * c2 * c * (1.0f / 120.0f);

    float c0z  = A * cexp_neg(0.00005f * z);  // A * exp(-DILL_B * z)
    float bulk = A * cexp_neg(0.0005f * z);   // A * exp(-ALPHA0 * z)
    float lat  = 1.0f;

    for (int it = 0; it < 50; ++it) {         // DILL_C*dt*LAMP = 0.1 exactly
        float e1 = ((((p5 * bulk + p4) * bulk + p3) * bulk + p2) * bulk + p1) * bulk + 1.0f;
        lat = lat * e1;
        float e2 = ((((q5 * lat + q4) * lat + q3) * lat + q2) * lat + q1) * lat + 1.0f;
        bulk = c0z * e2;
    }

    float x  = 1.0f - lat;
    float pm = x * x * x * x * x;
    const float am = 1.42648507485f;          // 0.99^5 * 6/4
    float rate = (am + 1.0f) * pm / (am + pm) * 10.0f + 0.8f;
    if (rate < 0.8f)  rate = 0.8f;
    if (rate > 10.0f) rate = 10.0f;
    return rate;
}

constexpr float G_at(int j) {
    float res = 0.0f, tt = 15.0f;
    for (int k = 0; k < 8; ++k) {
        float r = rate_at(j, k);
        float cur = r * tt;
        if (cur <= 20.0f) { res += cur; break; }
        res += 20.0f;
        tt -= 20.0f / r;
    }
    return res;
}

struct GTbl { float v[NG + 1]; };
constexpr GTbl make_tbl() {
    GTbl t{};
    for (int j = 0; j <= NG; ++j) t.v[j] = G_at(j);
    return t;
}
__device__ constexpr GTbl g_tbl = make_tbl();
__device__ constexpr float G_LAST = make_tbl().v[NG];   // G[64] as immediate

// Register-table lookup: G[i] for i in [0,64], table split across lanes.
__device__ __forceinline__ float tbl_get(int i, float ga, float gb) {
    float va = __shfl_sync(0xffffffffu, ga, i & 31);
    float vb = __shfl_sync(0xffffffffu, gb, i & 31);
    float v  = (i < 32) ? va : vb;
    return (i < NG) ? v : G_LAST;             // i == 64 edge
}

__device__ __forceinline__ float lerp_one(float a, float ga, float gb) {
    float xs = a * (float)NG;
    int   i  = (int)xs;                       // in [0,63] for a in [0,1)
    float v0 = tbl_get(i,     ga, gb);
    float v1 = tbl_get(i + 1, ga, gb);
    return fmaf(xs - (float)i, v1 - v0, v0);
}

__global__ __launch_bounds__(256) void develop_kernel(
        const float2* __restrict__ aerial2, float2* __restrict__ out2, int n2) {
    int lane = threadIdx.x & 31;
    float ga = g_tbl.v[lane];                 // G[0..31]
    float gb = g_tbl.v[lane + 32];            // G[32..63]

    int t = blockIdx.x * 256 + threadIdx.x;
    if (t >= n2) return;

    float2 A = __ldg(&aerial2[t]);
    float2 o;
    o.x = lerp_one(A.x, ga, gb);
    o.y = lerp_one(A.y, ga, gb);
    out2[t] = o;
}

extern "C" void kernel_launch(void* const* d_in, const int* in_sizes, int n_in,
                              void* d_out, int out_size) {
    const float* aerial = (const float*)d_in[0];
    float* out = (float*)d_out;
    int n  = in_sizes[0];          // 524288
    int n2 = n >> 1;               // 262144 threads = 1024 blocks x 256

    develop_kernel<<<(n2 + 255) / 256, 256>>>((const float2*)aerial,
                                              (float2*)out, n2);
}